// round 4
// baseline (speedup 1.0000x reference)
#include <cuda_runtime.h>
#include <cuda_bf16.h>
#include <cstdint>

#define COULOMB_K   14.3996454784936f
#define N_CAP       524288
#define SMEM_NODES  114688                 // 224 KB of u16 in shared memory
#define SMEM_BYTES  (SMEM_NODES * 2)
#define BLOCK       512
#define GRID        152

// u16 fixed-point sigma^2 table: q = sigma^2 * 16384
__device__ unsigned short g_sig2[N_CAP];

// ---------------- prologue: quantize sigma^2, zero output ----------------
__global__ void prep_kernel(const float* __restrict__ sigma,
                            float* __restrict__ out, int n_nodes) {
    int i = (blockIdx.x * blockDim.x + threadIdx.x) * 4;
#pragma unroll
    for (int k = 0; k < 4; k++) {
        int j = i + k;
        if (j < N_CAP) {
            float s2 = 0.0f;
            if (j < n_nodes) {
                float s = sigma[j];
                s2 = s * s;
                out[j] = 0.0f;
            }
            unsigned int q = __float2uint_rn(s2 * 16384.0f);
            g_sig2[j] = (unsigned short)(q > 65535u ? 65535u : q);
        }
    }
}

// gather sigma^2: shared memory for low indices (off the L1tex pipe), LDG otherwise
__device__ __forceinline__ uint32_t gat(const unsigned short* __restrict__ s_tab,
                                        int idx) {
    uint32_t v;
    if ((unsigned)idx < (unsigned)SMEM_NODES) v = s_tab[idx];
    else                                      v = __ldg(&g_sig2[idx]);
    return v;
}

// usum = q(ss^2)+q(sd^2);  2*(ss^2+sd^2) = usum / 8192
__device__ __forceinline__ void edge_compute(float r, uint32_t usum, int d,
                                             float* __restrict__ out) {
    float g2  = (float)usum * (1.0f / 8192.0f);
    float arg = r * rsqrtf(g2);                  // r / (sqrt2 * gamma)
    float x = r * 0.2f;                          // r / CUTOFF
    float p = fmaf(-6.0f, x, 15.0f);
    p = fmaf(p, x, -10.0f);
    float fcut = fmaf(x * x * x, p, 1.0f);       // 1 -10x^3 +15x^4 -6x^5
    fcut = (r <= 5.0f) ? fcut : 0.0f;
    float t = erff(arg) * fcut * __fdividef(1.0f, r);
    atomicAdd(out + d, t);                       // REDG
}

extern __shared__ unsigned short s_tab[];

__global__ void __launch_bounds__(BLOCK, 1)
edge_kernel(const float* __restrict__ bond,
            const int*   __restrict__ src,
            const int*   __restrict__ dst,
            float*       __restrict__ out,
            int n8, int n_edges) {
    // Stage first SMEM_NODES entries of the table into shared memory (coalesced)
    {
        const uint4* gt = reinterpret_cast<const uint4*>(g_sig2);
        uint4* st = reinterpret_cast<uint4*>(s_tab);
        for (int i = threadIdx.x; i < SMEM_BYTES / 16; i += BLOCK) st[i] = gt[i];
    }
    __syncthreads();

    const float4* bond4 = reinterpret_cast<const float4*>(bond);
    const int4*   src4  = reinterpret_cast<const int4*>(src);
    const int4*   dst4  = reinterpret_cast<const int4*>(dst);

    int stride = gridDim.x * BLOCK;
    for (int t = blockIdx.x * BLOCK + threadIdx.x; t < n8; t += stride) {
        long base = (long)t * 2;

        float4 rA = __ldcs(bond4 + base);
        float4 rB = __ldcs(bond4 + base + 1);
        int4   sA = __ldcs(src4 + base);
        int4   sB = __ldcs(src4 + base + 1);
        int4   dA = __ldcs(dst4 + base);
        int4   dB = __ldcs(dst4 + base + 1);

        int si[8] = {sA.x, sA.y, sA.z, sA.w, sB.x, sB.y, sB.z, sB.w};
        int di[8] = {dA.x, dA.y, dA.z, dA.w, dB.x, dB.y, dB.z, dB.w};
        float rr[8] = {rA.x, rA.y, rA.z, rA.w, rB.x, rB.y, rB.z, rB.w};

        uint32_t us[8], ud[8];
#pragma unroll
        for (int j = 0; j < 8; j++) us[j] = gat(s_tab, si[j]);
#pragma unroll
        for (int j = 0; j < 8; j++) ud[j] = gat(s_tab, di[j]);
#pragma unroll
        for (int j = 0; j < 8; j++)
            edge_compute(rr[j], us[j] + ud[j], di[j], out);
    }

    // scalar tail (n_edges % 8)
    if (blockIdx.x == 0) {
        for (int e = n8 * 8 + threadIdx.x; e < n_edges; e += BLOCK) {
            uint32_t a = gat(s_tab, src[e]) + gat(s_tab, dst[e]);
            edge_compute(bond[e], a, dst[e], out);
        }
    }
}

// ---------------- epilogue: out[i] *= K * charge[i] ----------------
__global__ void scale_kernel(const float* __restrict__ charge,
                             float* __restrict__ out, int n) {
    int i = blockIdx.x * blockDim.x + threadIdx.x;
    if (i < n) out[i] *= COULOMB_K * charge[i];
}

extern "C" void kernel_launch(void* const* d_in, const int* in_sizes, int n_in,
                              void* d_out, int out_size) {
    const float* charge    = (const float*)d_in[0];
    const float* sigma     = (const float*)d_in[1];
    const float* bond_dist = (const float*)d_in[2];
    const int*   src       = (const int*)d_in[3];
    const int*   dst       = (const int*)d_in[4];
    float* out = (float*)d_out;

    int n_nodes = in_sizes[0];
    int n_edges = in_sizes[2];

    {
        int work = (N_CAP + 3) / 4;
        prep_kernel<<<(work + 255) / 256, 256>>>(sigma, out, n_nodes);
    }

    cudaFuncSetAttribute(edge_kernel,
                         cudaFuncAttributeMaxDynamicSharedMemorySize, SMEM_BYTES);
    int n8 = n_edges / 8;
    edge_kernel<<<GRID, BLOCK, SMEM_BYTES>>>(bond_dist, src, dst, out,
                                             n8, n_edges);

    {
        scale_kernel<<<(n_nodes + 255) / 256, 256>>>(charge, out, n_nodes);
    }
}

// round 5
// speedup vs baseline: 1.5492x; 1.5492x over previous
#include <cuda_runtime.h>
#include <cuda_bf16.h>
#include <cstdint>

#define COULOMB_K   14.3996454784936f
#define N_CAP       524288
#define BLOCK       256

// u16 fixed-point sigma^2 table: q = sigma^2 * 16384  (sigma^2 < 2.26)
__device__ unsigned short g_sig2[N_CAP];

// ---------------- prologue: quantize sigma^2, zero output ----------------
__global__ void prep_kernel(const float* __restrict__ sigma,
                            float* __restrict__ out, int n_nodes) {
    int i = blockIdx.x * blockDim.x + threadIdx.x;
    if (i < N_CAP) {
        float s2 = 0.0f;
        if (i < n_nodes) {
            float s = sigma[i];
            s2 = s * s;
            out[i] = 0.0f;
        }
        unsigned int q = __float2uint_rn(s2 * 16384.0f);
        g_sig2[i] = (unsigned short)(q > 65535u ? 65535u : q);
    }
}

__device__ __forceinline__ unsigned short tbl(int idx) {
    return __ldg(&g_sig2[idx]);
}

// usum = q(ss^2)+q(sd^2);  2*(ss^2+sd^2) = usum / 8192
__device__ __forceinline__ float edge_msg(float r, uint32_t usum) {
    float g2  = (float)usum * (1.0f / 8192.0f);
    float arg = r * rsqrtf(g2);                  // r / (sqrt2 * gamma)
    float x = r * 0.2f;                          // r / CUTOFF
    float p = fmaf(-6.0f, x, 15.0f);
    p = fmaf(p, x, -10.0f);
    float fcut = fmaf(x * x * x, p, 1.0f);       // 1 -10x^3 +15x^4 -6x^5
    fcut = (r <= 5.0f) ? fcut : 0.0f;
    return erff(arg) * fcut * __fdividef(1.0f, r);
}

// 8 edges/thread: streams -> 16 gathers -> 8 FP messages -> 8 back-to-back REDs
__global__ void __launch_bounds__(BLOCK)
edge_kernel(const float* __restrict__ bond,
            const int*   __restrict__ src,
            const int*   __restrict__ dst,
            float*       __restrict__ out,
            int n8) {
    int t = blockIdx.x * BLOCK + threadIdx.x;
    if (t >= n8) return;
    long base = (long)t * 2;

    const float4* bond4 = reinterpret_cast<const float4*>(bond);
    const int4*   src4  = reinterpret_cast<const int4*>(src);
    const int4*   dst4  = reinterpret_cast<const int4*>(dst);

    // streaming loads, evict-first
    int4   sA = __ldcs(src4 + base);
    int4   sB = __ldcs(src4 + base + 1);
    int4   dA = __ldcs(dst4 + base);
    int4   dB = __ldcs(dst4 + base + 1);
    float4 rA = __ldcs(bond4 + base);
    float4 rB = __ldcs(bond4 + base + 1);

    int   di[8] = {dA.x, dA.y, dA.z, dA.w, dB.x, dB.y, dB.z, dB.w};
    int   si[8] = {sA.x, sA.y, sA.z, sA.w, sB.x, sB.y, sB.z, sB.w};
    float rr[8] = {rA.x, rA.y, rA.z, rA.w, rB.x, rB.y, rB.z, rB.w};

    // all 16 scattered gathers issued contiguously (max MLP over L2 latency)
    uint32_t us[8], ud[8];
#pragma unroll
    for (int j = 0; j < 8; j++) us[j] = tbl(si[j]);
#pragma unroll
    for (int j = 0; j < 8; j++) ud[j] = tbl(di[j]);

    // FP phase: all 8 messages into registers (no scattered ops interleaved)
    float m[8];
#pragma unroll
    for (int j = 0; j < 8; j++) m[j] = edge_msg(rr[j], us[j] + ud[j]);

    // scatter phase: 8 REDs back-to-back
#pragma unroll
    for (int j = 0; j < 8; j++) atomicAdd(out + di[j], m[j]);
}

__global__ void edge_tail_kernel(const float* __restrict__ bond,
                                 const int*   __restrict__ src,
                                 const int*   __restrict__ dst,
                                 float*       __restrict__ out,
                                 int start, int n_edges) {
    int e = start + blockIdx.x * blockDim.x + threadIdx.x;
    if (e < n_edges) {
        uint32_t a = (uint32_t)tbl(src[e]) + (uint32_t)tbl(dst[e]);
        atomicAdd(out + dst[e], edge_msg(bond[e], a));
    }
}

// ---------------- epilogue: out[i] *= K * charge[i] ----------------
__global__ void scale_kernel(const float* __restrict__ charge,
                             float* __restrict__ out, int n) {
    int i = blockIdx.x * blockDim.x + threadIdx.x;
    if (i < n) out[i] *= COULOMB_K * charge[i];
}

extern "C" void kernel_launch(void* const* d_in, const int* in_sizes, int n_in,
                              void* d_out, int out_size) {
    const float* charge    = (const float*)d_in[0];
    const float* sigma     = (const float*)d_in[1];
    const float* bond_dist = (const float*)d_in[2];
    const int*   src       = (const int*)d_in[3];
    const int*   dst       = (const int*)d_in[4];
    float* out = (float*)d_out;

    int n_nodes = in_sizes[0];
    int n_edges = in_sizes[2];

    prep_kernel<<<(N_CAP + BLOCK - 1) / BLOCK, BLOCK>>>(sigma, out, n_nodes);

    int n8 = n_edges / 8;
    if (n8 > 0) {
        int blocks = (n8 + BLOCK - 1) / BLOCK;
        edge_kernel<<<blocks, BLOCK>>>(bond_dist, src, dst, out, n8);
    }
    int tail_start = n8 * 8;
    if (tail_start < n_edges) {
        int tail = n_edges - tail_start;
        edge_tail_kernel<<<(tail + BLOCK - 1) / BLOCK, BLOCK>>>(
            bond_dist, src, dst, out, tail_start, n_edges);
    }

    scale_kernel<<<(n_nodes + BLOCK - 1) / BLOCK, BLOCK>>>(charge, out, n_nodes);
}